// round 16
// baseline (speedup 1.0000x reference)
#include <cuda_runtime.h>
#include <cuda_bf16.h>

#define NF    2048
#define NF4   (NF / 4)       // 512 float4 per row
#define GRID  592            // 148 SMs x 4 CTAs, exactly balanced
#define P     296            // row chunks == GRID/2
#define NC    12             // rows cached in smem per CTA (12*4KB = 48KB)
#define SMEM_BYTES (NC * 256 * 16)
#define EPS   1e-6f

// Scratch (__device__ globals per allocation-free rule)
__device__ __align__(16) float g_ps[P * NF];   // partial sums   [p][c]
__device__ __align__(16) float g_pq[P * NF];   // partial sumsq  [p][c]
__device__ __align__(16) float g_mean[NF];
__device__ __align__(16) float g_istd[NF];

// Grid-barrier counters (zero-init; last CTA resets for graph replays)
__device__ unsigned g_bar1;
__device__ unsigned g_bar2;
__device__ unsigned g_bar3;

__device__ __forceinline__ unsigned ld_acquire(unsigned* p) {
    unsigned v;
    asm volatile("ld.acquire.gpu.u32 %0, [%1];" : "=r"(v) : "l"(p) : "memory");
    return v;
}

__device__ __forceinline__ void st_release(unsigned* p, unsigned v) {
    asm volatile("st.release.gpu.u32 [%0], %1;" :: "l"(p), "r"(v) : "memory");
}

__device__ __forceinline__ void grid_barrier(unsigned* bar) {
    __syncthreads();
    __threadfence();
    if (threadIdx.x == 0) {
        atomicAdd(bar, 1u);
        while (ld_acquire(bar) < GRID) { __nanosleep(32); }
    }
    __syncthreads();
}

__global__ void __launch_bounds__(256, 4)
fused_kernel(const float* __restrict__ x, float* __restrict__ out, int rows) {
    extern __shared__ float4 tile[];        // [NC * 256] = 48KB

    int bid  = blockIdx.x;
    int cb   = bid & 1;                 // column half: 0 or 1
    int p    = bid >> 1;                // row chunk 0..P-1
    int tid  = threadIdx.x;
    int col4 = cb * 256 + tid;          // 0..NF4-1
    int r0   = (int)(((long long)p * rows) / P);
    int r1   = (int)(((long long)(p + 1) * rows) / P);
    int nc   = min(NC, r1 - r0);
    int rc_end = r0 + nc;               // rows [r0, rc_end) cached in smem

    const float4* xp = reinterpret_cast<const float4*>(x);

    // -------- Phase 1: column reduce (MLP=8) + smem-cache first NC rows ----
    float sx = 0.f, sy = 0.f, sz = 0.f, sw = 0.f;
    float qx = 0.f, qy = 0.f, qz = 0.f, qw = 0.f;

    int r = r0;
    #pragma unroll 1
    for (; r + 8 <= r1; r += 8) {
        size_t base = (size_t)r * NF4 + col4;
        float4 v[8];
        #pragma unroll
        for (int k = 0; k < 8; k++) v[k] = xp[base + (size_t)k * NF4];
        #pragma unroll
        for (int k = 0; k < 8; k++) {
            sx += v[k].x; sy += v[k].y; sz += v[k].z; sw += v[k].w;
            qx += v[k].x * v[k].x; qy += v[k].y * v[k].y;
            qz += v[k].z * v[k].z; qw += v[k].w * v[k].w;
        }
        #pragma unroll
        for (int k = 0; k < 8; k++) {
            if (r + k < rc_end) tile[(r + k - r0) * 256 + tid] = v[k];
        }
    }
    #pragma unroll 1
    for (; r < r1; ++r) {
        float4 v = xp[(size_t)r * NF4 + col4];
        sx += v.x; sy += v.y; sz += v.z; sw += v.w;
        qx += v.x*v.x; qy += v.y*v.y; qz += v.z*v.z; qw += v.w*v.w;
        if (r < rc_end) tile[(r - r0) * 256 + tid] = v;
    }

    {
        size_t o = (size_t)p * NF4 + col4;
        reinterpret_cast<float4*>(g_ps)[o] = make_float4(sx, sy, sz, sw);
        reinterpret_cast<float4*>(g_pq)[o] = make_float4(qx, qy, qz, qw);
    }

    grid_barrier(&g_bar1);

    // ------- Phase 2: stats. CTAs 0..511 each own col4 group == bid -------
    if (bid < NF4) {
        __shared__ float4 s_s[8];
        __shared__ float4 s_q[8];
        int t = threadIdx.x;
        float4 a = reinterpret_cast<const float4*>(g_ps)[(size_t)t * NF4 + bid];
        float4 b = reinterpret_cast<const float4*>(g_pq)[(size_t)t * NF4 + bid];
        if (t + 256 < P) {
            float4 a2 = reinterpret_cast<const float4*>(g_ps)[(size_t)(t + 256) * NF4 + bid];
            float4 b2 = reinterpret_cast<const float4*>(g_pq)[(size_t)(t + 256) * NF4 + bid];
            a.x += a2.x; a.y += a2.y; a.z += a2.z; a.w += a2.w;
            b.x += b2.x; b.y += b2.y; b.z += b2.z; b.w += b2.w;
        }
        #pragma unroll
        for (int off = 16; off > 0; off >>= 1) {
            a.x += __shfl_xor_sync(0xffffffffu, a.x, off);
            a.y += __shfl_xor_sync(0xffffffffu, a.y, off);
            a.z += __shfl_xor_sync(0xffffffffu, a.z, off);
            a.w += __shfl_xor_sync(0xffffffffu, a.w, off);
            b.x += __shfl_xor_sync(0xffffffffu, b.x, off);
            b.y += __shfl_xor_sync(0xffffffffu, b.y, off);
            b.z += __shfl_xor_sync(0xffffffffu, b.z, off);
            b.w += __shfl_xor_sync(0xffffffffu, b.w, off);
        }
        int warp = t >> 5, lane = t & 31;
        if (lane == 0) { s_s[warp] = a; s_q[warp] = b; }
        __syncthreads();
        if (warp == 0 && lane < 8) {
            a = s_s[lane]; b = s_q[lane];
            #pragma unroll
            for (int off = 4; off > 0; off >>= 1) {
                a.x += __shfl_xor_sync(0xffu, a.x, off);
                a.y += __shfl_xor_sync(0xffu, a.y, off);
                a.z += __shfl_xor_sync(0xffu, a.z, off);
                a.w += __shfl_xor_sync(0xffu, a.w, off);
                b.x += __shfl_xor_sync(0xffu, b.x, off);
                b.y += __shfl_xor_sync(0xffu, b.y, off);
                b.z += __shfl_xor_sync(0xffu, b.z, off);
                b.w += __shfl_xor_sync(0xffu, b.w, off);
            }
            if (lane == 0) {
                float n = (float)rows;
                float inv_n = 1.0f / n;
                float inv_n1 = 1.0f / (n - 1.0f);
                float4 m, is;
                m.x = a.x * inv_n; m.y = a.y * inv_n;
                m.z = a.z * inv_n; m.w = a.w * inv_n;
                is.x = rsqrtf((b.x - n * m.x * m.x) * inv_n1 + EPS);
                is.y = rsqrtf((b.y - n * m.y * m.y) * inv_n1 + EPS);
                is.z = rsqrtf((b.z - n * m.z * m.z) * inv_n1 + EPS);
                is.w = rsqrtf((b.w - n * m.w * m.w) * inv_n1 + EPS);
                reinterpret_cast<float4*>(g_mean)[bid] = m;
                reinterpret_cast<float4*>(g_istd)[bid] = is;
            }
        }
    } else {
        __syncthreads();   // keep barrier arrival shape uniform
    }

    grid_barrier(&g_bar2);

    // ---- Phase 3: normalize own tile: cached rows from smem, rest global --
    {
        float4 m = reinterpret_cast<const float4*>(g_mean)[col4];
        float4 s = reinterpret_cast<const float4*>(g_istd)[col4];
        float4* op = reinterpret_cast<float4*>(out);

        // cached rows: smem reads, global writes
        #pragma unroll 2
        for (int rr = r0; rr < rc_end; ++rr) {
            float4 v = tile[(rr - r0) * 256 + tid];
            float4 o;
            o.x = (v.x - m.x) * s.x; o.y = (v.y - m.y) * s.y;
            o.z = (v.z - m.z) * s.z; o.w = (v.w - m.w) * s.w;
            op[(size_t)rr * NF4 + col4] = o;
        }

        // uncached rows: global reads (MLP=4), global writes
        int rr = rc_end;
        #pragma unroll 1
        for (; rr + 4 <= r1; rr += 4) {
            size_t base = (size_t)rr * NF4 + col4;
            float4 v0 = xp[base];
            float4 v1 = xp[base + 1 * NF4];
            float4 v2 = xp[base + 2 * NF4];
            float4 v3 = xp[base + 3 * NF4];
            float4 o0, o1, o2, o3;
            o0.x = (v0.x - m.x) * s.x; o0.y = (v0.y - m.y) * s.y;
            o0.z = (v0.z - m.z) * s.z; o0.w = (v0.w - m.w) * s.w;
            o1.x = (v1.x - m.x) * s.x; o1.y = (v1.y - m.y) * s.y;
            o1.z = (v1.z - m.z) * s.z; o1.w = (v1.w - m.w) * s.w;
            o2.x = (v2.x - m.x) * s.x; o2.y = (v2.y - m.y) * s.y;
            o2.z = (v2.z - m.z) * s.z; o2.w = (v2.w - m.w) * s.w;
            o3.x = (v3.x - m.x) * s.x; o3.y = (v3.y - m.y) * s.y;
            o3.z = (v3.z - m.z) * s.z; o3.w = (v3.w - m.w) * s.w;
            op[base]           = o0;
            op[base + 1 * NF4] = o1;
            op[base + 2 * NF4] = o2;
            op[base + 3 * NF4] = o3;
        }
        #pragma unroll 1
        for (; rr < r1; ++rr) {
            size_t i = (size_t)rr * NF4 + col4;
            float4 v = xp[i];
            float4 o;
            o.x = (v.x - m.x) * s.x; o.y = (v.y - m.y) * s.y;
            o.z = (v.z - m.z) * s.z; o.w = (v.w - m.w) * s.w;
            op[i] = o;
        }
    }

    // ---------------- Reset barriers for next graph replay ----------------
    __syncthreads();
    if (threadIdx.x == 0) {
        unsigned prev = atomicAdd(&g_bar3, 1u);
        if (prev == GRID - 1) {
            st_release(&g_bar1, 0u);
            st_release(&g_bar2, 0u);
            st_release(&g_bar3, 0u);
        }
    }
}

extern "C" void kernel_launch(void* const* d_in, const int* in_sizes, int n_in,
                              void* d_out, int out_size) {
    const float* x = (const float*)d_in[0];
    float* out = (float*)d_out;
    int rows = in_sizes[0] / NF;     // 8192

    static int smem_set = 0;
    if (!smem_set) {
        cudaFuncSetAttribute(fused_kernel,
                             cudaFuncAttributeMaxDynamicSharedMemorySize,
                             SMEM_BYTES);
        smem_set = 1;
    }

    fused_kernel<<<GRID, 256, SMEM_BYTES>>>(x, out, rows);
}